// round 1
// baseline (speedup 1.0000x reference)
#include <cuda_runtime.h>
#include <cstdint>
#include <math.h>

// Problem constants
#define Bn 2048
#define Sn 50
#define En 256
#define Hn 512
#define Gn 2048        // 4*H
#define Wn 256
#define Ln 50
#define ND (Gn + Wn)   // 2304 : [dec gates | blend2]

// ---------------- device scratch (no allocations allowed) ----------------
__device__ float g_h[Bn * Hn];
__device__ float g_c[Bn * Hn];
__device__ float g_gates[Bn * ND];
__device__ float g_enc[(size_t)Bn * Sn * Hn];     // encoder hidden states [B,S,H]
__device__ float g_blend1[(size_t)Bn * Sn * Wn];  // [B,S,W]
__device__ float g_scores[Bn * Sn];
__device__ unsigned char g_mask[Bn * Sn];
__device__ float g_encW[Gn * (En + Hn)];          // [4H, E+H] concat(Wih,Whh)
__device__ float g_decW[ND * Hn];                 // [2304, H] concat(dec_Whh, W2)
__device__ float g_bias_enc[Gn];
__device__ float g_bias_dec[ND];

// ---------------- prep ----------------
__global__ void k_prep(const float* __restrict__ eWih, const float* __restrict__ eWhh,
                       const float* __restrict__ ebih, const float* __restrict__ ebhh,
                       const float* __restrict__ dWhh, const float* __restrict__ dbih,
                       const float* __restrict__ dbhh, const float* __restrict__ W2) {
    int idx = blockIdx.x * blockDim.x + threadIdx.x;
    if (idx < Gn * (En + Hn)) {
        int n = idx / (En + Hn), k = idx % (En + Hn);
        g_encW[idx] = (k < En) ? eWih[n * En + k] : eWhh[n * Hn + (k - En)];
    }
    if (idx < ND * Hn) {
        int n = idx / Hn, k = idx % Hn;
        g_decW[idx] = (n < Gn) ? dWhh[idx] : W2[(n - Gn) * Hn + k];
    }
    if (idx < Gn) g_bias_enc[idx] = ebih[idx] + ebhh[idx];
    if (idx < ND) g_bias_dec[idx] = (idx < Gn) ? (dbih[idx] + dbhh[idx]) : 0.0f;
}

__global__ void k_init() {
    int idx = blockIdx.x * blockDim.x + threadIdx.x;
    if (idx < Bn * Hn) { g_h[idx] = 0.0f; g_c[idx] = 0.0f; }
    if (idx < Bn * Sn) g_mask[idx] = 0;
}

__global__ void k_decinit() {
    int idx = blockIdx.x * blockDim.x + threadIdx.x;
    if (idx < Bn * Hn) {
        int b = idx / Hn, j = idx % Hn;
        g_h[idx] = 0.0f;
        g_c[idx] = g_enc[((size_t)b * Sn + (Sn - 1)) * Hn + j];  // c0 = last encoder h
    }
}

// ---------------- SGEMM: C[M,N] = A[M,K] * B[N,K]^T (+bias) ----------------
// GATHER: A[m,k] = emb[inp[m*Sn]*En + k] for k<En, else Ah[m*lda + k-En]
template <bool GATHER>
__global__ __launch_bounds__(256, 2) void sgemm128(
    int M, int N, int K,
    const float* __restrict__ Ah, int lda,
    const float* __restrict__ emb, const int* __restrict__ inp,
    const float* __restrict__ Bw,
    const float* __restrict__ bias,
    float* __restrict__ C, int ldc) {
    __shared__ float As[8][128];
    __shared__ float Bs[8][128];
    const int tid = threadIdx.x;
    const int bm = blockIdx.y * 128, bn = blockIdx.x * 128;
    const int lr = tid >> 1;
    const int lc = (tid & 1) << 2;
    const int arow = bm + lr, brow = bn + lr;
    int erow = 0;
    if (GATHER) erow = inp[arow * Sn];
    const int tx = tid & 15, ty = tid >> 4;

    float acc[8][8];
#pragma unroll
    for (int i = 0; i < 8; i++)
#pragma unroll
        for (int j = 0; j < 8; j++) acc[i][j] = 0.0f;

    for (int k0 = 0; k0 < K; k0 += 8) {
        float4 av, bv;
        if (GATHER && k0 < En)
            av = *reinterpret_cast<const float4*>(emb + (size_t)erow * En + k0 + lc);
        else
            av = *reinterpret_cast<const float4*>(Ah + (size_t)arow * lda + (k0 + lc - (GATHER ? En : 0)));
        bv = *reinterpret_cast<const float4*>(Bw + (size_t)brow * K + k0 + lc);
        As[lc + 0][lr] = av.x; As[lc + 1][lr] = av.y; As[lc + 2][lr] = av.z; As[lc + 3][lr] = av.w;
        Bs[lc + 0][lr] = bv.x; Bs[lc + 1][lr] = bv.y; Bs[lc + 2][lr] = bv.z; Bs[lc + 3][lr] = bv.w;
        __syncthreads();
#pragma unroll
        for (int kk = 0; kk < 8; kk++) {
            float a[8], b[8];
            *(float4*)&a[0] = *(const float4*)&As[kk][ty * 4];
            *(float4*)&a[4] = *(const float4*)&As[kk][64 + ty * 4];
            *(float4*)&b[0] = *(const float4*)&Bs[kk][tx * 4];
            *(float4*)&b[4] = *(const float4*)&Bs[kk][64 + tx * 4];
#pragma unroll
            for (int i = 0; i < 8; i++)
#pragma unroll
                for (int j = 0; j < 8; j++) acc[i][j] = fmaf(a[i], b[j], acc[i][j]);
        }
        __syncthreads();
    }
#pragma unroll
    for (int i = 0; i < 8; i++) {
        int m = bm + ((i < 4) ? (ty * 4 + i) : (64 + ty * 4 + i - 4));
#pragma unroll
        for (int jh = 0; jh < 2; jh++) {
            int n = bn + (jh ? (64 + tx * 4) : (tx * 4));
            float4 v;
            v.x = acc[i][jh * 4 + 0]; v.y = acc[i][jh * 4 + 1];
            v.z = acc[i][jh * 4 + 2]; v.w = acc[i][jh * 4 + 3];
            if (bias) { v.x += bias[n]; v.y += bias[n + 1]; v.z += bias[n + 2]; v.w += bias[n + 3]; }
            *reinterpret_cast<float4*>(C + (size_t)m * ldc + n) = v;
        }
    }
}

// ---------------- LSTM cell elementwise ----------------
__device__ __forceinline__ float sigf(float x) { return 1.0f / (1.0f + expf(-x)); }

__global__ void k_cell(int ld, int t /* encoder step to store, -1 for decoder */) {
    int idx = blockIdx.x * blockDim.x + threadIdx.x;
    if (idx >= Bn * Hn) return;
    int b = idx / Hn, j = idx % Hn;
    const float* gr = g_gates + (size_t)b * ld;
    float gi = gr[j], gf = gr[Hn + j], gg = gr[2 * Hn + j], go = gr[3 * Hn + j];
    float cn = sigf(gf) * g_c[idx] + sigf(gi) * tanhf(gg);
    float hn = sigf(go) * tanhf(cn);
    g_c[idx] = cn;
    g_h[idx] = hn;
    if (t >= 0) g_enc[((size_t)b * Sn + t) * Hn + j] = hn;
}

// ---------------- attention scores ----------------
__global__ void k_scores(const float* __restrict__ vt) {
    int b = blockIdx.x, tid = threadIdx.x;  // 256 threads
    __shared__ float sb[Wn], sv[Wn];
    sb[tid] = g_gates[(size_t)b * ND + Gn + tid];  // blend2 row (fused into dec GEMM)
    sv[tid] = vt[tid];
    __syncthreads();
    int warp = tid >> 5, lane = tid & 31;
    for (int s = warp; s < Sn; s += 8) {
        const float* row = g_blend1 + ((size_t)b * Sn + s) * Wn;
        float acc = 0.0f;
#pragma unroll
        for (int q = 0; q < 8; q++) {
            int w = lane + q * 32;
            acc += tanhf(row[w] + sb[w]) * sv[w];
        }
        for (int off = 16; off; off >>= 1) acc += __shfl_xor_sync(0xffffffffu, acc, off);
        if (lane == 0) g_scores[b * Sn + s] = acc;
    }
}

// ---------------- threefry2x32 (JAX-compatible) ----------------
__device__ __forceinline__ uint32_t rotl32(uint32_t v, int d) { return (v << d) | (v >> (32 - d)); }

__device__ uint32_t threefry_xor(uint32_t k0, uint32_t k1, uint32_t x0, uint32_t x1) {
    uint32_t ks2 = k0 ^ k1 ^ 0x1BD11BDAu;
    x0 += k0; x1 += k1;
    const int ra[4] = {13, 15, 26, 6}, rb[4] = {17, 29, 16, 24};
#pragma unroll
    for (int i = 0; i < 4; i++) { x0 += x1; x1 = rotl32(x1, ra[i]); x1 ^= x0; }
    x0 += k1; x1 += ks2 + 1u;
#pragma unroll
    for (int i = 0; i < 4; i++) { x0 += x1; x1 = rotl32(x1, rb[i]); x1 ^= x0; }
    x0 += ks2; x1 += k0 + 2u;
#pragma unroll
    for (int i = 0; i < 4; i++) { x0 += x1; x1 = rotl32(x1, ra[i]); x1 ^= x0; }
    x0 += k0; x1 += k1 + 3u;
#pragma unroll
    for (int i = 0; i < 4; i++) { x0 += x1; x1 = rotl32(x1, rb[i]); x1 ^= x0; }
    x0 += k1; x1 += ks2 + 4u;
#pragma unroll
    for (int i = 0; i < 4; i++) { x0 += x1; x1 = rotl32(x1, ra[i]); x1 ^= x0; }
    x0 += ks2; x1 += k0 + 5u;
    return x0 ^ x1;  // partitionable 32-bit random_bits = out0 ^ out1
}

__device__ __forceinline__ float gumbel_from_bits(uint32_t bits) {
    const float TINY = 1.17549435e-38f;
    float f = __uint_as_float((bits >> 9) | 0x3f800000u) - 1.0f;  // [0,1)
    float u = f * (1.0f - TINY) + TINY;
    u = fmaxf(TINY, u);
    return -logf(-logf(u));
}

// ---------------- masked log-softmax + categorical sample ----------------
__global__ void k_sample(int l, uint32_t key0, uint32_t key1,
                         float* __restrict__ probs, float* __restrict__ tour) {
    int gw = (blockIdx.x * blockDim.x + threadIdx.x) >> 5;
    int lane = threadIdx.x & 31;
    if (gw >= Bn) return;
    int b = gw;
    int s0 = lane, s1 = lane + 32;
    const float NEG = -3.4e38f;
    float x0 = g_mask[b * Sn + s0] ? -100000.0f : g_scores[b * Sn + s0];
    float x1 = NEG;
    if (s1 < Sn) x1 = g_mask[b * Sn + s1] ? -100000.0f : g_scores[b * Sn + s1];
    float m = fmaxf(x0, x1);
    for (int off = 16; off; off >>= 1) m = fmaxf(m, __shfl_xor_sync(0xffffffffu, m, off));
    float sum = expf(x0 - m) + ((s1 < Sn) ? expf(x1 - m) : 0.0f);
    for (int off = 16; off; off >>= 1) sum += __shfl_xor_sync(0xffffffffu, sum, off);
    float lse = logf(sum);
    float lp0 = x0 - m - lse;
    float lp1 = x1 - m - lse;
    float* prow = probs + ((size_t)b * Ln + l) * Sn;
    prow[s0] = lp0;
    if (s1 < Sn) prow[s1] = lp1;
    float v0 = lp0 + gumbel_from_bits(threefry_xor(key0, key1, 0u, (uint32_t)(b * Sn + s0)));
    float v1 = NEG;
    if (s1 < Sn) v1 = lp1 + gumbel_from_bits(threefry_xor(key0, key1, 0u, (uint32_t)(b * Sn + s1)));
    float bv; int bi;
    if (v1 > v0) { bv = v1; bi = s1; } else { bv = v0; bi = s0; }  // tie -> lower index
    for (int off = 16; off; off >>= 1) {
        float ov = __shfl_xor_sync(0xffffffffu, bv, off);
        int   oi = __shfl_xor_sync(0xffffffffu, bi, off);
        if (ov > bv || (ov == bv && oi < bi)) { bv = ov; bi = oi; }
    }
    if (lane == 0) {
        tour[(size_t)b * Ln + l] = (float)bi;
        g_mask[b * Sn + bi] = 1;
    }
}

// ---------------- host threefry (to derive the 50 step keys) ----------------
static void tf_host(uint32_t k0, uint32_t k1, uint32_t x0, uint32_t x1,
                    uint32_t& o0, uint32_t& o1) {
    uint32_t ks2 = k0 ^ k1 ^ 0x1BD11BDAu;
    x0 += k0; x1 += k1;
    const int ra[4] = {13, 15, 26, 6}, rb[4] = {17, 29, 16, 24};
    auto rl = [](uint32_t v, int d) { return (v << d) | (v >> (32 - d)); };
    for (int i = 0; i < 4; i++) { x0 += x1; x1 = rl(x1, ra[i]); x1 ^= x0; }
    x0 += k1; x1 += ks2 + 1u;
    for (int i = 0; i < 4; i++) { x0 += x1; x1 = rl(x1, rb[i]); x1 ^= x0; }
    x0 += ks2; x1 += k0 + 2u;
    for (int i = 0; i < 4; i++) { x0 += x1; x1 = rl(x1, ra[i]); x1 ^= x0; }
    x0 += k0; x1 += k1 + 3u;
    for (int i = 0; i < 4; i++) { x0 += x1; x1 = rl(x1, rb[i]); x1 ^= x0; }
    x0 += k1; x1 += ks2 + 4u;
    for (int i = 0; i < 4; i++) { x0 += x1; x1 = rl(x1, ra[i]); x1 ^= x0; }
    x0 += ks2; x1 += k0 + 5u;
    o0 = x0; o1 = x1;
}

extern "C" void kernel_launch(void* const* d_in, const int* in_sizes, int n_in,
                              void* d_out, int out_size) {
    const int*   input = (const int*)d_in[0];
    const float* emb   = (const float*)d_in[1];
    const float* eWih  = (const float*)d_in[2];
    const float* eWhh  = (const float*)d_in[3];
    const float* ebih  = (const float*)d_in[4];
    const float* ebhh  = (const float*)d_in[5];
    // d_in[6] = dec_Wih (unused: decoder input is always zero)
    const float* dWhh  = (const float*)d_in[7];
    const float* dbih  = (const float*)d_in[8];
    const float* dbhh  = (const float*)d_in[9];
    const float* W1    = (const float*)d_in[10];
    // d_in[11] = W2 (folded into decW), d_in[12] = vt
    const float* W2    = (const float*)d_in[11];
    const float* vt    = (const float*)d_in[12];

    float* out   = (float*)d_out;
    float* probs = out;                               // [B, L, S]
    float* tour  = out + (size_t)Bn * Ln * Sn;        // [B, L] as float

    float *p_h, *p_gates, *p_enc, *p_b1, *p_encW, *p_decW, *p_be, *p_bd;
    cudaGetSymbolAddress((void**)&p_h, g_h);
    cudaGetSymbolAddress((void**)&p_gates, g_gates);
    cudaGetSymbolAddress((void**)&p_enc, g_enc);
    cudaGetSymbolAddress((void**)&p_b1, g_blend1);
    cudaGetSymbolAddress((void**)&p_encW, g_encW);
    cudaGetSymbolAddress((void**)&p_decW, g_decW);
    cudaGetSymbolAddress((void**)&p_be, g_bias_enc);
    cudaGetSymbolAddress((void**)&p_bd, g_bias_dec);

    const int EWB = (Gn * (En + Hn) + 255) / 256;
    const int BHB = (Bn * Hn + 255) / 256;

    k_prep<<<EWB, 256>>>(eWih, eWhh, ebih, ebhh, dWhh, dbih, dbhh, W2);
    k_init<<<BHB, 256>>>();

    // -------- encoder: 50 steps --------
    for (int t = 0; t < Sn; t++) {
        sgemm128<true><<<dim3(Gn / 128, Bn / 128), 256>>>(
            Bn, Gn, En + Hn, p_h, Hn, emb, input + t, p_encW, p_be, p_gates, Gn);
        k_cell<<<BHB, 256>>>(Gn, t);
    }

    // -------- blend1 = enc_states @ W1^T : [B*S, W] --------
    sgemm128<false><<<dim3(Wn / 128, (Bn * Sn) / 128), 256>>>(
        Bn * Sn, Wn, Hn, p_enc, Hn, nullptr, nullptr, W1, nullptr, p_b1, Wn);

    // -------- decoder init: h=0, c=enc_seq[-1] --------
    k_decinit<<<BHB, 256>>>();

    // pre-loop GEMM: h=0 -> gates = bias_dec (blend2 part unused this round)
    sgemm128<false><<<dim3(ND / 128, Bn / 128), 256>>>(
        Bn, ND, Hn, p_h, Hn, nullptr, nullptr, p_decW, p_bd, p_gates, ND);

    // step keys: keys[l] = threefry2x32((0,42), (0,l))  (partitionable split)
    uint32_t K0[Ln], K1[Ln];
    for (int l = 0; l < Ln; l++) tf_host(0u, 42u, 0u, (uint32_t)l, K0[l], K1[l]);

    for (int l = 0; l < Ln; l++) {
        k_cell<<<BHB, 256>>>(ND, -1);  // h_l, c_l from gates_l
        // fused: [gates_{l+1} | blend2_l] = h_l @ [decWhh; W2]^T + [bias_dec | 0]
        sgemm128<false><<<dim3(ND / 128, Bn / 128), 256>>>(
            Bn, ND, Hn, p_h, Hn, nullptr, nullptr, p_decW, p_bd, p_gates, ND);
        k_scores<<<Bn, 256>>>(vt);
        k_sample<<<(Bn * 32) / 256, 256>>>(l, K0[l], K1[l], probs, tour);
    }
    (void)in_sizes; (void)n_in; (void)out_size;
}

// round 2
// speedup vs baseline: 1.5394x; 1.5394x over previous
#include <cuda_runtime.h>
#include <cstdint>
#include <math.h>

typedef unsigned long long ull;

// Problem constants
#define Bn 2048
#define Sn 50
#define En 256
#define Hn 512
#define Gn 2048        // 4*H
#define Wn 256
#define Ln 50
#define ND (Gn + Wn)   // 2304 : [interleaved dec gates | W2 rows]
#define Vn 51

// ---------------- device scratch (no allocations allowed) ----------------
__device__ float g_h0[Bn * Hn];
__device__ float g_h1[Bn * Hn];
__device__ float g_c[Bn * Hn];
__device__ float g_enc[(size_t)Bn * Sn * Hn];     // encoder hidden states [B,S,H]
__device__ float g_blend1[(size_t)Bn * Sn * Wn];  // [B,S,W]
__device__ float g_blend2[Bn * Wn];
__device__ float g_scores[Bn * Sn];
__device__ unsigned char g_mask[Bn * Sn];
__device__ float g_encW2[Gn * Hn];                // interleaved [4j+g, k] of enc_Whh
__device__ float g_decW2[ND * Hn];                // interleaved dec_Whh rows then W2 rows
__device__ float g_bias_dec2[Gn];                 // interleaved decoder bias
__device__ float g_P[Vn * Gn];                    // emb@Wih^T + enc bias, interleaved cols

// ---------------- f32x2 helpers ----------------
__device__ __forceinline__ ull pk(float x, float y) {
    ull r; asm("mov.b64 %0,{%1,%2};" : "=l"(r) : "f"(x), "f"(y)); return r;
}
__device__ __forceinline__ void fma2(ull& d, ull a, ull b) {
    asm("fma.rn.f32x2 %0,%1,%2,%3;" : "=l"(d) : "l"(a), "l"(b), "l"(d));
}
__device__ __forceinline__ float2 up(ull v) {
    float2 f; asm("mov.b64 {%0,%1},%2;" : "=f"(f.x), "=f"(f.y) : "l"(v)); return f;
}

__device__ __forceinline__ float sigf(float x) { return 1.0f / (1.0f + expf(-x)); }

// ---------------- prep: weight reorder + interleave ----------------
__global__ void k_prep(const float* __restrict__ eWhh,
                       const float* __restrict__ dWhh, const float* __restrict__ dbih,
                       const float* __restrict__ dbhh, const float* __restrict__ W2) {
    int idx = blockIdx.x * blockDim.x + threadIdx.x;
    if (idx < Gn * Hn) {
        int n2 = idx / Hn, k = idx % Hn;
        int g = n2 & 3, j = n2 >> 2;
        g_encW2[idx] = eWhh[(g * Hn + j) * Hn + k];
    }
    if (idx < ND * Hn) {
        int n2 = idx / Hn, k = idx % Hn;
        if (n2 < Gn) {
            int g = n2 & 3, j = n2 >> 2;
            g_decW2[idx] = dWhh[(g * Hn + j) * Hn + k];
        } else {
            g_decW2[idx] = W2[(size_t)(n2 - Gn) * Hn + k];
        }
    }
    if (idx < Gn) {
        int g = idx & 3, j = idx >> 2;
        int r = g * Hn + j;
        g_bias_dec2[idx] = dbih[r] + dbhh[r];
    }
}

// P[v][n2] = emb[v] . Wih[r] + bih[r] + bhh[r],  r = (n2&3)*H + (n2>>2)
__global__ void k_prep_P(const float* __restrict__ emb, const float* __restrict__ eWih,
                         const float* __restrict__ ebih, const float* __restrict__ ebhh) {
    int idx = blockIdx.x * blockDim.x + threadIdx.x;
    if (idx >= Vn * Gn) return;
    int v = idx / Gn, n2 = idx % Gn;
    int g = n2 & 3, j = n2 >> 2;
    int r = g * Hn + j;
    const float4* e = reinterpret_cast<const float4*>(emb + (size_t)v * En);
    const float4* w = reinterpret_cast<const float4*>(eWih + (size_t)r * En);
    float s = 0.0f;
    #pragma unroll 8
    for (int k = 0; k < En / 4; k++) {
        float4 a = __ldg(e + k), b = __ldg(w + k);
        s += a.x * b.x + a.y * b.y + a.z * b.z + a.w * b.w;
    }
    g_P[idx] = s + ebih[r] + ebhh[r];
}

__global__ void k_init() {
    int idx = blockIdx.x * blockDim.x + threadIdx.x;
    if (idx < Bn * Hn) { g_h0[idx] = 0.0f; g_c[idx] = 0.0f; }
    if (idx < Bn * Sn) g_mask[idx] = 0;
}

// decoder first cell: h_prev = 0 -> gates = bias only; c0 = enc last hidden
__global__ void k_dec0() {
    int idx = blockIdx.x * blockDim.x + threadIdx.x;
    if (idx >= Bn * Hn) return;
    int b = idx / Hn, j = idx % Hn;
    float gi = g_bias_dec2[4 * j + 0], gf = g_bias_dec2[4 * j + 1];
    float gg = g_bias_dec2[4 * j + 2], go = g_bias_dec2[4 * j + 3];
    float c0 = g_enc[((size_t)b * Sn + (Sn - 1)) * Hn + j];
    float cn = sigf(gf) * c0 + sigf(gi) * tanhf(gg);
    g_c[idx] = cn;
    g_h0[idx] = sigf(go) * tanhf(cn);
}

// ---------------- fused GEMM (FFMA2, double-buffered) ----------------
// C[M,N] = A[M,512] * Bw[N,512]^T ; epilogue per MODE:
//   MODE 0: plain store to Cout (ldc)
//   MODE 1: encoder: add P[token], LSTM cell -> hout, cst, enc[:,t,:]
//   MODE 2: decoder: bn<Gn -> add bias2 + cell -> hout,cst ; bn>=Gn -> store blend2
template <int MODE>
__global__ __launch_bounds__(256, 2) void gemm_fused(
    const float* __restrict__ A,
    const float* __restrict__ Bw,
    const float* __restrict__ bias2,
    const float* __restrict__ P,
    const int* __restrict__ tok,
    float* __restrict__ Cout, int ldc,
    float* __restrict__ hout,
    float* __restrict__ cst,
    float* __restrict__ enc, int t) {
    __shared__ float As[2][8][128];
    __shared__ float Bs[2][8][128];
    const int tid = threadIdx.x;
    const int bm = blockIdx.y * 128, bn = blockIdx.x * 128;
    const int lr = tid >> 1, lc = (tid & 1) << 2;
    const int tx = tid & 15, ty = tid >> 4;
    const float* Aa = A + (size_t)(bm + lr) * Hn + lc;
    const float* Bb = Bw + (size_t)(bn + lr) * Hn + lc;

    ull acc[8][4];
#pragma unroll
    for (int i = 0; i < 8; i++)
#pragma unroll
        for (int p = 0; p < 4; p++) acc[i][p] = 0ull;

    {   // preload k-tile 0
        float4 av = *reinterpret_cast<const float4*>(Aa);
        float4 bv = *reinterpret_cast<const float4*>(Bb);
        As[0][lc + 0][lr] = av.x; As[0][lc + 1][lr] = av.y;
        As[0][lc + 2][lr] = av.z; As[0][lc + 3][lr] = av.w;
        Bs[0][lc + 0][lr] = bv.x; Bs[0][lc + 1][lr] = bv.y;
        Bs[0][lc + 2][lr] = bv.z; Bs[0][lc + 3][lr] = bv.w;
    }
    __syncthreads();

#pragma unroll 1
    for (int kt = 0; kt < Hn / 8; kt++) {
        const int cur = kt & 1;
        float4 av, bv;
        if (kt < Hn / 8 - 1) {
            av = *reinterpret_cast<const float4*>(Aa + (kt + 1) * 8);
            bv = *reinterpret_cast<const float4*>(Bb + (kt + 1) * 8);
        }
#pragma unroll
        for (int kk = 0; kk < 8; kk++) {
            float4 aq0 = *reinterpret_cast<const float4*>(&As[cur][kk][ty * 4]);
            float4 aq1 = *reinterpret_cast<const float4*>(&As[cur][kk][64 + ty * 4]);
            float4 bq0 = *reinterpret_cast<const float4*>(&Bs[cur][kk][tx * 4]);
            float4 bq1 = *reinterpret_cast<const float4*>(&Bs[cur][kk][64 + tx * 4]);
            ull b2[4] = {pk(bq0.x, bq0.y), pk(bq0.z, bq0.w),
                         pk(bq1.x, bq1.y), pk(bq1.z, bq1.w)};
            ull a2[8] = {pk(aq0.x, aq0.x), pk(aq0.y, aq0.y), pk(aq0.z, aq0.z), pk(aq0.w, aq0.w),
                         pk(aq1.x, aq1.x), pk(aq1.y, aq1.y), pk(aq1.z, aq1.z), pk(aq1.w, aq1.w)};
#pragma unroll
            for (int i = 0; i < 8; i++)
#pragma unroll
                for (int p = 0; p < 4; p++) fma2(acc[i][p], a2[i], b2[p]);
        }
        if (kt < Hn / 8 - 1) {
            const int nxt = cur ^ 1;
            As[nxt][lc + 0][lr] = av.x; As[nxt][lc + 1][lr] = av.y;
            As[nxt][lc + 2][lr] = av.z; As[nxt][lc + 3][lr] = av.w;
            Bs[nxt][lc + 0][lr] = bv.x; Bs[nxt][lc + 1][lr] = bv.y;
            Bs[nxt][lc + 2][lr] = bv.z; Bs[nxt][lc + 3][lr] = bv.w;
            __syncthreads();
        }
    }

    // ---------------- epilogue ----------------
#pragma unroll
    for (int i = 0; i < 8; i++) {
        int m = bm + ((i < 4) ? (ty * 4 + i) : (64 + ty * 4 + (i - 4)));
        int tokv = 0;
        if (MODE == 1) tokv = tok[m * Sn];
#pragma unroll
        for (int jh = 0; jh < 2; jh++) {
            int n = bn + jh * 64 + tx * 4;
            float2 q0 = up(acc[i][jh * 2]);
            float2 q1 = up(acc[i][jh * 2 + 1]);
            float g0 = q0.x, g1 = q0.y, g2 = q1.x, g3 = q1.y;
            if (MODE == 0) {
                float4 v = {g0, g1, g2, g3};
                *reinterpret_cast<float4*>(Cout + (size_t)m * ldc + n) = v;
            } else if (MODE == 2 && bn >= Gn) {
                float4 v = {g0, g1, g2, g3};
                *reinterpret_cast<float4*>(Cout + (size_t)m * Wn + (n - Gn)) = v;
            } else {
                if (MODE == 1) {
                    const float* pr = P + (size_t)tokv * Gn + n;
                    g0 += pr[0]; g1 += pr[1]; g2 += pr[2]; g3 += pr[3];
                } else {
                    g0 += bias2[n]; g1 += bias2[n + 1]; g2 += bias2[n + 2]; g3 += bias2[n + 3];
                }
                int j = n >> 2;
                float co = cst[m * Hn + j];
                float cn = sigf(g1) * co + sigf(g0) * tanhf(g2);
                float hn = sigf(g3) * tanhf(cn);
                cst[m * Hn + j] = cn;
                hout[m * Hn + j] = hn;
                if (MODE == 1) enc[((size_t)m * Sn + t) * Hn + j] = hn;
            }
        }
    }
}

// ---------------- attention scores ----------------
__global__ void k_scores(const float* __restrict__ vt) {
    int b = blockIdx.x, tid = threadIdx.x;  // 256 threads
    __shared__ float sb[Wn], sv[Wn];
    sb[tid] = g_blend2[b * Wn + tid];
    sv[tid] = vt[tid];
    __syncthreads();
    int warp = tid >> 5, lane = tid & 31;
    for (int s = warp; s < Sn; s += 8) {
        const float* row = g_blend1 + ((size_t)b * Sn + s) * Wn;
        float acc = 0.0f;
#pragma unroll
        for (int q = 0; q < 8; q++) {
            int w = lane + q * 32;
            acc += tanhf(row[w] + sb[w]) * sv[w];
        }
        for (int off = 16; off; off >>= 1) acc += __shfl_xor_sync(0xffffffffu, acc, off);
        if (lane == 0) g_scores[b * Sn + s] = acc;
    }
}

// ---------------- threefry2x32 (JAX-compatible) ----------------
__device__ __forceinline__ uint32_t rotl32(uint32_t v, int d) { return (v << d) | (v >> (32 - d)); }

__device__ uint32_t threefry_xor(uint32_t k0, uint32_t k1, uint32_t x0, uint32_t x1) {
    uint32_t ks2 = k0 ^ k1 ^ 0x1BD11BDAu;
    x0 += k0; x1 += k1;
    const int ra[4] = {13, 15, 26, 6}, rb[4] = {17, 29, 16, 24};
#pragma unroll
    for (int i = 0; i < 4; i++) { x0 += x1; x1 = rotl32(x1, ra[i]); x1 ^= x0; }
    x0 += k1; x1 += ks2 + 1u;
#pragma unroll
    for (int i = 0; i < 4; i++) { x0 += x1; x1 = rotl32(x1, rb[i]); x1 ^= x0; }
    x0 += ks2; x1 += k0 + 2u;
#pragma unroll
    for (int i = 0; i < 4; i++) { x0 += x1; x1 = rotl32(x1, ra[i]); x1 ^= x0; }
    x0 += k0; x1 += k1 + 3u;
#pragma unroll
    for (int i = 0; i < 4; i++) { x0 += x1; x1 = rotl32(x1, rb[i]); x1 ^= x0; }
    x0 += k1; x1 += ks2 + 4u;
#pragma unroll
    for (int i = 0; i < 4; i++) { x0 += x1; x1 = rotl32(x1, ra[i]); x1 ^= x0; }
    x0 += ks2; x1 += k0 + 5u;
    return x0 ^ x1;  // partitionable 32-bit random_bits = out0 ^ out1
}

__device__ __forceinline__ float gumbel_from_bits(uint32_t bits) {
    const float TINY = 1.17549435e-38f;
    float f = __uint_as_float((bits >> 9) | 0x3f800000u) - 1.0f;  // [0,1)
    float u = f * (1.0f - TINY) + TINY;
    u = fmaxf(TINY, u);
    return -logf(-logf(u));
}

// ---------------- masked log-softmax + categorical sample ----------------
__global__ void k_sample(int l, uint32_t key0, uint32_t key1,
                         float* __restrict__ probs, float* __restrict__ tour) {
    int gw = (blockIdx.x * blockDim.x + threadIdx.x) >> 5;
    int lane = threadIdx.x & 31;
    if (gw >= Bn) return;
    int b = gw;
    int s0 = lane, s1 = lane + 32;
    const float NEG = -3.4e38f;
    float x0 = g_mask[b * Sn + s0] ? -100000.0f : g_scores[b * Sn + s0];
    float x1 = NEG;
    if (s1 < Sn) x1 = g_mask[b * Sn + s1] ? -100000.0f : g_scores[b * Sn + s1];
    float m = fmaxf(x0, x1);
    for (int off = 16; off; off >>= 1) m = fmaxf(m, __shfl_xor_sync(0xffffffffu, m, off));
    float sum = expf(x0 - m) + ((s1 < Sn) ? expf(x1 - m) : 0.0f);
    for (int off = 16; off; off >>= 1) sum += __shfl_xor_sync(0xffffffffu, sum, off);
    float lse = logf(sum);
    float lp0 = x0 - m - lse;
    float lp1 = x1 - m - lse;
    float* prow = probs + ((size_t)b * Ln + l) * Sn;
    prow[s0] = lp0;
    if (s1 < Sn) prow[s1] = lp1;
    float v0 = lp0 + gumbel_from_bits(threefry_xor(key0, key1, 0u, (uint32_t)(b * Sn + s0)));
    float v1 = NEG;
    if (s1 < Sn) v1 = lp1 + gumbel_from_bits(threefry_xor(key0, key1, 0u, (uint32_t)(b * Sn + s1)));
    float bv; int bi;
    if (v1 > v0) { bv = v1; bi = s1; } else { bv = v0; bi = s0; }
    for (int off = 16; off; off >>= 1) {
        float ov = __shfl_xor_sync(0xffffffffu, bv, off);
        int   oi = __shfl_xor_sync(0xffffffffu, bi, off);
        if (ov > bv || (ov == bv && oi < bi)) { bv = ov; bi = oi; }
    }
    if (lane == 0) {
        tour[(size_t)b * Ln + l] = (float)bi;
        g_mask[b * Sn + bi] = 1;
    }
}

// ---------------- host threefry ----------------
static void tf_host(uint32_t k0, uint32_t k1, uint32_t x0, uint32_t x1,
                    uint32_t& o0, uint32_t& o1) {
    uint32_t ks2 = k0 ^ k1 ^ 0x1BD11BDAu;
    x0 += k0; x1 += k1;
    const int ra[4] = {13, 15, 26, 6}, rb[4] = {17, 29, 16, 24};
    auto rl = [](uint32_t v, int d) { return (v << d) | (v >> (32 - d)); };
    for (int i = 0; i < 4; i++) { x0 += x1; x1 = rl(x1, ra[i]); x1 ^= x0; }
    x0 += k1; x1 += ks2 + 1u;
    for (int i = 0; i < 4; i++) { x0 += x1; x1 = rl(x1, rb[i]); x1 ^= x0; }
    x0 += ks2; x1 += k0 + 2u;
    for (int i = 0; i < 4; i++) { x0 += x1; x1 = rl(x1, ra[i]); x1 ^= x0; }
    x0 += k0; x1 += k1 + 3u;
    for (int i = 0; i < 4; i++) { x0 += x1; x1 = rl(x1, rb[i]); x1 ^= x0; }
    x0 += k1; x1 += ks2 + 4u;
    for (int i = 0; i < 4; i++) { x0 += x1; x1 = rl(x1, ra[i]); x1 ^= x0; }
    x0 += ks2; x1 += k0 + 5u;
    o0 = x0; o1 = x1;
}

extern "C" void kernel_launch(void* const* d_in, const int* in_sizes, int n_in,
                              void* d_out, int out_size) {
    const int*   input = (const int*)d_in[0];
    const float* emb   = (const float*)d_in[1];
    const float* eWih  = (const float*)d_in[2];
    const float* eWhh  = (const float*)d_in[3];
    const float* ebih  = (const float*)d_in[4];
    const float* ebhh  = (const float*)d_in[5];
    // d_in[6] = dec_Wih (unused: decoder input is always zero)
    const float* dWhh  = (const float*)d_in[7];
    const float* dbih  = (const float*)d_in[8];
    const float* dbhh  = (const float*)d_in[9];
    const float* W1    = (const float*)d_in[10];
    const float* W2    = (const float*)d_in[11];
    const float* vt    = (const float*)d_in[12];

    float* out   = (float*)d_out;
    float* probs = out;                               // [B, L, S]
    float* tour  = out + (size_t)Bn * Ln * Sn;        // [B, L] as float

    float *p_h0, *p_h1, *p_c, *p_enc, *p_b1, *p_b2, *p_encW2, *p_decW2, *p_bd2, *p_P;
    cudaGetSymbolAddress((void**)&p_h0, g_h0);
    cudaGetSymbolAddress((void**)&p_h1, g_h1);
    cudaGetSymbolAddress((void**)&p_c, g_c);
    cudaGetSymbolAddress((void**)&p_enc, g_enc);
    cudaGetSymbolAddress((void**)&p_b1, g_blend1);
    cudaGetSymbolAddress((void**)&p_b2, g_blend2);
    cudaGetSymbolAddress((void**)&p_encW2, g_encW2);
    cudaGetSymbolAddress((void**)&p_decW2, g_decW2);
    cudaGetSymbolAddress((void**)&p_bd2, g_bias_dec2);
    cudaGetSymbolAddress((void**)&p_P, g_P);

    const int BHB = (Bn * Hn + 255) / 256;

    k_prep<<<(ND * Hn + 255) / 256, 256>>>(eWhh, dWhh, dbih, dbhh, W2);
    k_prep_P<<<(Vn * Gn + 255) / 256, 256>>>(emb, eWih, ebih, ebhh);
    k_init<<<BHB, 256>>>();

    // -------- encoder: 50 fused GEMM+cell steps, K=512 --------
    for (int t = 0; t < Sn; t++) {
        float* hin  = (t & 1) ? p_h1 : p_h0;
        float* hout = (t & 1) ? p_h0 : p_h1;
        gemm_fused<1><<<dim3(Gn / 128, Bn / 128), 256>>>(
            hin, p_encW2, nullptr, p_P, input + t,
            nullptr, 0, hout, p_c, p_enc, t);
    }

    // -------- blend1 = enc_states @ W1^T : [B*S, W] --------
    gemm_fused<0><<<dim3(Wn / 128, (Bn * Sn) / 128), 256>>>(
        p_enc, W1, nullptr, nullptr, nullptr,
        p_b1, Wn, nullptr, nullptr, nullptr, 0);

    // -------- decoder first cell (h_prev = 0) --------
    k_dec0<<<BHB, 256>>>();

    // step keys: keys[l] = threefry2x32((0,42), (0,l))
    uint32_t K0[Ln], K1[Ln];
    for (int l = 0; l < Ln; l++) tf_host(0u, 42u, 0u, (uint32_t)l, K0[l], K1[l]);

    for (int l = 0; l < Ln; l++) {
        float* hin  = (l & 1) ? p_h1 : p_h0;
        float* hout = (l & 1) ? p_h0 : p_h1;
        // [gates_{l+2} | blend2_l] = h @ [decWhh_int; W2]^T ; cell fused
        gemm_fused<2><<<dim3(ND / 128, Bn / 128), 256>>>(
            hin, p_decW2, p_bd2, nullptr, nullptr,
            p_b2, Wn, hout, p_c, nullptr, 0);
        k_scores<<<Bn, 256>>>(vt);
        k_sample<<<(Bn * 32) / 256, 256>>>(l, K0[l], K1[l], probs, tour);
    }
    (void)in_sizes; (void)n_in; (void)out_size;
}